// round 16
// baseline (speedup 1.0000x reference)
#include <cuda_runtime.h>
#include <cuda_fp16.h>
#include <cstdint>

#define N_PTS 32768
#define M_PTS 8192
#define D_DIM 64
#define BM 128
#define BN 128                        // y-subtile rows
#define ITER_BN 256                   // y rows per loop iteration (2 subtiles)
#define NITER (M_PTS / ITER_BN)       // 32
#define NBLOCKS (N_PTS / BM)          // 256

// dynamic smem layout (bytes)
#define OFF_XH     0                  // 16384
#define OFF_Y      16384              // 2 iter-bufs x 32768 (each = 2 subtiles)
#define OFF_BS     81920              // 2 * 256 * 4
#define OFF_X2S    83968              // 128 * 4
#define OFF_ROWRED 84480              // 4 * 128 * 4
#define OFF_RED    86528              // 16
#define SMEM_TOTAL 86544

__device__ __half g_yh[M_PTS * D_DIM];
__device__ float g_b[M_PTS];
__device__ float g_partials[NBLOCKS];

__device__ __forceinline__ uint32_t smem_u32(const void* p) {
    uint32_t a;
    asm("{ .reg .u64 t; cvta.to.shared.u64 t, %1; cvt.u32.u64 %0, t; }" : "=r"(a) : "l"(p));
    return a;
}
__device__ __forceinline__ uint32_t h2_u32(__half2 h) {
    uint32_t u;
    *reinterpret_cast<__half2*>(&u) = h;
    return u;
}

#define CP_ASYNC16(s, g) \
    asm volatile("cp.async.cg.shared.global [%0], [%1], 16;" :: "r"(s), "l"(g))
#define CP_COMMIT()  asm volatile("cp.async.commit_group;" ::: "memory")
#define CP_WAIT(N)   asm volatile("cp.async.wait_group %0;" :: "n"(N) : "memory")

#define LDSM4(r, addr) \
    asm volatile("ldmatrix.sync.aligned.m8n8.x4.shared.b16 {%0,%1,%2,%3}, [%4];" \
                 : "=r"((r)[0]), "=r"((r)[1]), "=r"((r)[2]), "=r"((r)[3]) : "r"(addr))

#define MMA_F16(c, a, b0, b1) \
    asm volatile("mma.sync.aligned.m16n8k16.row.col.f32.f16.f16.f32 " \
                 "{%0,%1,%2,%3},{%4,%5,%6,%7},{%8,%9},{%0,%1,%2,%3};" \
                 : "+f"((c)[0]), "+f"((c)[1]), "+f"((c)[2]), "+f"((c)[3]) \
                 : "r"((a)[0]), "r"((a)[1]), "r"((a)[2]), "r"((a)[3]), "r"(b0), "r"(b1))

// ---------------------------------------------------------------------------
// Prep: fp16 conversion of y; b_j = ||y_j||^2 - psi_j (fp32, exact)
// ---------------------------------------------------------------------------
__global__ void prep_y_kernel(const float* __restrict__ y,
                              const float* __restrict__ psi) {
    int i4 = blockIdx.x * blockDim.x + threadIdx.x;   // 0 .. M*D/4-1
    float4 v = ((const float4*)y)[i4];
    __half2* yh2 = (__half2*)g_yh;
    yh2[i4 * 2]     = __halves2half2(__float2half(v.x), __float2half(v.y));
    yh2[i4 * 2 + 1] = __halves2half2(__float2half(v.z), __float2half(v.w));
    if (i4 < M_PTS) {
        const float4* yr = (const float4*)(y + (size_t)i4 * D_DIM);
        float s = 0.f;
#pragma unroll
        for (int q = 0; q < 16; q++) {
            float4 w = yr[q];
            s = fmaf(w.x, w.x, s); s = fmaf(w.y, w.y, s);
            s = fmaf(w.z, w.z, s); s = fmaf(w.w, w.w, s);
        }
        g_b[i4] = s - psi[i4];
    }
}

// ---------------------------------------------------------------------------
// Main: fp16 mma (f32 acc), 256-row y iterations (2 subtiles per barrier),
// double-buffered with race-free ordering: wait -> barrier -> prefetch ->
// compute. Chunked accumulators, fused min-epilogue.
// 8 warps: wm = w>>2 (2), wn = w&3 (4); warp subtile 64 x 32.
// ---------------------------------------------------------------------------
__global__ __launch_bounds__(256, 2)
void semidual_mma_kernel(const float* __restrict__ x) {
    extern __shared__ char smem[];
    const uint32_t sb = smem_u32(smem);
    const int tid  = threadIdx.x;
    const int lane = tid & 31;
    const int w    = tid >> 5;
    const int wm   = w >> 2;
    const int wn   = w & 3;
    const int i0   = blockIdx.x * BM;

    // cp.async one [128 x 64] fp16 y-subtile with swizzled stores
    auto tile_cp = [&](int row0, uint32_t soff) {
        const char* gp = (const char*)(g_yh + (size_t)row0 * D_DIM);
#pragma unroll
        for (int it = 0; it < 4; it++) {
            int c   = it * 256 + tid;        // 0..1023
            int row = c >> 3, col = c & 7;
            uint32_t so = sb + soff + row * 128 + ((col ^ (row & 7)) << 4);
            CP_ASYNC16(so, gp + (size_t)c * 16);
        }
    };

    // convert x tile fp32 -> fp16 directly into swizzled smem
    {
        const float4* x4 = (const float4*)(x + (size_t)i0 * D_DIM);
#pragma unroll
        for (int it = 0; it < 4; it++) {
            int c   = it * 256 + tid;        // chunk 0..1023
            int row = c >> 3, col8 = c & 7;
            float4 v0 = x4[row * 16 + col8 * 2];
            float4 v1 = x4[row * 16 + col8 * 2 + 1];
            uint4 h;
            h.x = h2_u32(__halves2half2(__float2half(v0.x), __float2half(v0.y)));
            h.y = h2_u32(__halves2half2(__float2half(v0.z), __float2half(v0.w)));
            h.z = h2_u32(__halves2half2(__float2half(v1.x), __float2half(v1.y)));
            h.w = h2_u32(__halves2half2(__float2half(v1.z), __float2half(v1.w)));
            *(uint4*)(smem + OFF_XH + row * 128 + ((col8 ^ (row & 7)) << 4)) = h;
        }
    }

    // prologue: iteration-0 y (2 subtiles, ONE group); bs slot 0; x2
    tile_cp(0, OFF_Y);
    tile_cp(BN, OFF_Y + 16384);
    CP_COMMIT();
    {
        ((float*)(smem + OFF_BS))[tid] = g_b[tid];      // 256 b values, iter 0
        if (tid < BM) {
            const float4* xr = (const float4*)(x + (size_t)(i0 + tid) * D_DIM);
            float x2 = 0.f;
#pragma unroll
            for (int q = 0; q < 16; q++) {
                float4 v = xr[q];
                x2 = fmaf(v.x, v.x, x2); x2 = fmaf(v.y, v.y, x2);
                x2 = fmaf(v.z, v.z, x2); x2 = fmaf(v.w, v.w, x2);
            }
            ((float*)(smem + OFF_X2S))[tid] = x2;
        }
    }

    // per-lane invariant addressing pieces
    const uint32_t aoff  = (uint32_t)(wm * 64 + (lane & 15)) * 128;
    const int      cselA = lane >> 4;
    const int      axorA = (lane & 7);
    const uint32_t boff  = (uint32_t)(wn * 32 + ((lane >> 4) << 3) + (lane & 7)) * 128;
    const int      cselB = (lane >> 3) & 1;
    const int      bxorB = (lane & 7);
    const int      j0b   = wn * 32 + (lane & 3) * 2;

    float rmin[8];
#pragma unroll
    for (int r = 0; r < 8; r++) rmin[r] = 3.4e38f;

    for (int t = 0; t < NITER; t++) {
        const int b = t & 1, nb = b ^ 1;

        // 1) buffer b fully landed (only one group ever in flight)
        CP_WAIT(0);
        // 2) all warps finished iteration t-1 (done reading buffer nb & bs[nb])
        __syncthreads();
        // 3) now safe: prefetch iteration t+1 into nb (overlaps compute below)
        if (t + 1 < NITER) {
            tile_cp((t + 1) * ITER_BN,      OFF_Y + nb * 32768);
            tile_cp((t + 1) * ITER_BN + BN, OFF_Y + nb * 32768 + 16384);
            CP_COMMIT();
            ((float*)(smem + OFF_BS))[nb * ITER_BN + tid] = g_b[(t + 1) * ITER_BN + tid];
        }

        const uint32_t axh = sb + OFF_XH;

#pragma unroll
        for (int sub = 0; sub < 2; sub++) {
            const uint32_t yb  = sb + OFF_Y + b * 32768 + sub * 16384;
            const float* bsf = (const float*)(smem + OFF_BS) + b * ITER_BN + sub * BN;

#pragma unroll
            for (int mtc = 0; mtc < 2; mtc++) {
                float c[2][4][4];
#pragma unroll
                for (int mt = 0; mt < 2; mt++)
#pragma unroll
                    for (int nt = 0; nt < 4; nt++)
#pragma unroll
                        for (int q = 0; q < 4; q++) c[mt][nt][q] = 0.f;

#pragma unroll
                for (int kb = 0; kb < 4; kb++) {
                    const uint32_t ca = (uint32_t)(((2 * kb + cselA) ^ axorA) << 4);
                    const uint32_t cb = (uint32_t)(((2 * kb + cselB) ^ bxorB) << 4);
                    uint32_t a[2][4], bb[2][4];
#pragma unroll
                    for (int mt = 0; mt < 2; mt++)
                        LDSM4(a[mt], axh + aoff + (mtc * 2 + mt) * 2048 + ca);
#pragma unroll
                    for (int np = 0; np < 2; np++)
                        LDSM4(bb[np], yb + boff + np * 2048 + cb);
#pragma unroll
                    for (int mt = 0; mt < 2; mt++)
#pragma unroll
                        for (int nt = 0; nt < 4; nt++)
                            MMA_F16(c[mt][nt], a[mt], bb[nt >> 1][(nt & 1) * 2], bb[nt >> 1][(nt & 1) * 2 + 1]);
                }

                // fold this m-chunk into rmin
#pragma unroll
                for (int nt = 0; nt < 4; nt++) {
                    const float b0 = bsf[j0b + nt * 8];
                    const float b1 = bsf[j0b + nt * 8 + 1];
#pragma unroll
                    for (int mt = 0; mt < 2; mt++) {
                        const int mi = mtc * 2 + mt;
                        float v0 = fminf(fmaf(-2.f, c[mt][nt][0], b0), fmaf(-2.f, c[mt][nt][1], b1));
                        float v1 = fminf(fmaf(-2.f, c[mt][nt][2], b0), fmaf(-2.f, c[mt][nt][3], b1));
                        rmin[mi * 2]     = fminf(rmin[mi * 2], v0);
                        rmin[mi * 2 + 1] = fminf(rmin[mi * 2 + 1], v1);
                    }
                }
            }
        }
    }

    // min across the 4 j-lanes of each row group
#pragma unroll
    for (int r = 0; r < 8; r++) {
        rmin[r] = fminf(rmin[r], __shfl_xor_sync(0xffffffffu, rmin[r], 1));
        rmin[r] = fminf(rmin[r], __shfl_xor_sync(0xffffffffu, rmin[r], 2));
    }
    float* rowred = (float*)(smem + OFF_ROWRED);
    __syncthreads();
    if ((lane & 3) == 0) {
        const int g = lane >> 2;
#pragma unroll
        for (int mt = 0; mt < 4; mt++) {
            const int r0 = wm * 64 + mt * 16 + g;
            rowred[wn * BM + r0]     = rmin[mt * 2];
            rowred[wn * BM + r0 + 8] = rmin[mt * 2 + 1];
        }
    }
    __syncthreads();
    if (tid < BM) {
        float m = fminf(fminf(rowred[tid], rowred[BM + tid]),
                        fminf(rowred[2 * BM + tid], rowred[3 * BM + tid]));
        float v = ((const float*)(smem + OFF_X2S))[tid] + m;
#pragma unroll
        for (int s = 16; s >= 1; s >>= 1) v += __shfl_xor_sync(0xffffffffu, v, s);
        if (lane == 0) ((float*)(smem + OFF_RED))[tid >> 5] = v;
    }
    __syncthreads();
    if (tid == 0) {
        const float* rd = (const float*)(smem + OFF_RED);
        g_partials[blockIdx.x] = rd[0] + rd[1] + rd[2] + rd[3];
    }
}

// ---------------------------------------------------------------------------
// Finalize: deterministic reduction + mean(psi), vectorized
// ---------------------------------------------------------------------------
__global__ void finalize_kernel(const float* __restrict__ psi,
                                float* __restrict__ out) {
    __shared__ float sh[256];
    int tid = threadIdx.x;
    float s = 0.f;
    for (int b = tid; b < NBLOCKS; b += 256) s += g_partials[b];
    s *= (1.0f / N_PTS);
    float p = 0.f;
    const float4* p4 = (const float4*)psi;
#pragma unroll
    for (int q = 0; q < M_PTS / 4 / 256; q++) {
        float4 v = p4[q * 256 + tid];
        p += (v.x + v.y) + (v.z + v.w);
    }
    s = fmaf(p, 1.0f / M_PTS, s);
    sh[tid] = s;
    __syncthreads();
    for (int off = 128; off > 0; off >>= 1) {
        if (tid < off) sh[tid] += sh[tid + off];
        __syncthreads();
    }
    if (tid == 0) out[0] = sh[0];
}

extern "C" void kernel_launch(void* const* d_in, const int* in_sizes, int n_in,
                              void* d_out, int out_size) {
    (void)in_sizes; (void)n_in; (void)out_size;
    const float* x   = (const float*)d_in[0];   // [N, D]
    const float* y   = (const float*)d_in[1];   // [M, D]
    const float* psi = (const float*)d_in[2];   // [M]
    float* out = (float*)d_out;

    cudaFuncSetAttribute(semidual_mma_kernel,
                         cudaFuncAttributeMaxDynamicSharedMemorySize, SMEM_TOTAL);

    prep_y_kernel<<<(M_PTS * D_DIM / 4) / 256, 256>>>(y, psi);
    semidual_mma_kernel<<<NBLOCKS, 256, SMEM_TOTAL>>>(x);
    finalize_kernel<<<1, 256>>>(psi, out);
}

// round 17
// speedup vs baseline: 1.1271x; 1.1271x over previous
#include <cuda_runtime.h>
#include <cuda_fp16.h>
#include <cstdint>

#define N_PTS 32768
#define M_PTS 8192
#define D_DIM 64
#define BM 128
#define BN 128
#define NTILES (M_PTS / BN)          // 64
#define NBLOCKS (N_PTS / BM)         // 256

// dynamic smem layout (bytes)
#define OFF_XH     0                 // 16384
#define OFF_Y      16384             // 3 * 16384 (triple-buffered y)
#define OFF_BSH    65536             // 3 * 64 * 4 (half2 col-pair b values)
#define OFF_X2S    66304             // 128 * 4
#define OFF_ROWRED 66816             // 4 * 128 * 4
#define OFF_RED    68864             // 16
#define SMEM_TOTAL 68880

__device__ __half g_yh[M_PTS * D_DIM];
__device__ float g_b[M_PTS];
__device__ float g_partials[NBLOCKS];

__device__ __forceinline__ uint32_t smem_u32(const void* p) {
    uint32_t a;
    asm("{ .reg .u64 t; cvta.to.shared.u64 t, %1; cvt.u32.u64 %0, t; }" : "=r"(a) : "l"(p));
    return a;
}
__device__ __forceinline__ uint32_t h2_u32(__half2 h) {
    uint32_t u;
    *reinterpret_cast<__half2*>(&u) = h;
    return u;
}
__device__ __forceinline__ __half2 u32_h2(uint32_t u) {
    __half2 h;
    *reinterpret_cast<uint32_t*>(&h) = u;
    return h;
}

#define CP_ASYNC16(s, g) \
    asm volatile("cp.async.cg.shared.global [%0], [%1], 16;" :: "r"(s), "l"(g))
#define CP_COMMIT()  asm volatile("cp.async.commit_group;" ::: "memory")
#define CP_WAIT(N)   asm volatile("cp.async.wait_group %0;" :: "n"(N) : "memory")

#define LDSM4(r, addr) \
    asm volatile("ldmatrix.sync.aligned.m8n8.x4.shared.b16 {%0,%1,%2,%3}, [%4];" \
                 : "=r"((r)[0]), "=r"((r)[1]), "=r"((r)[2]), "=r"((r)[3]) : "r"(addr))

// fp16-accumulate MMA: c packs (row r | row r+8) x (col j, j+1) as 2 half2 regs
#define MMA_F16ACC(c, a, b0, b1) \
    asm volatile("mma.sync.aligned.m16n8k16.row.col.f16.f16.f16.f16 " \
                 "{%0,%1},{%2,%3,%4,%5},{%6,%7},{%0,%1};" \
                 : "+r"((c)[0]), "+r"((c)[1]) \
                 : "r"((a)[0]), "r"((a)[1]), "r"((a)[2]), "r"((a)[3]), "r"(b0), "r"(b1))

// ---------------------------------------------------------------------------
// Prep: fp16 conversion of y; b_j = ||y_j||^2 - psi_j (fp32, exact)
// ---------------------------------------------------------------------------
__global__ void prep_y_kernel(const float* __restrict__ y,
                              const float* __restrict__ psi) {
    int i4 = blockIdx.x * blockDim.x + threadIdx.x;   // 0 .. M*D/4-1
    float4 v = ((const float4*)y)[i4];
    __half2* yh2 = (__half2*)g_yh;
    yh2[i4 * 2]     = __halves2half2(__float2half(v.x), __float2half(v.y));
    yh2[i4 * 2 + 1] = __halves2half2(__float2half(v.z), __float2half(v.w));
    if (i4 < M_PTS) {
        const float4* yr = (const float4*)(y + (size_t)i4 * D_DIM);
        float s = 0.f;
#pragma unroll
        for (int q = 0; q < 16; q++) {
            float4 w = yr[q];
            s = fmaf(w.x, w.x, s); s = fmaf(w.y, w.y, s);
            s = fmaf(w.z, w.z, s); s = fmaf(w.w, w.w, s);
        }
        g_b[i4] = s - psi[i4];
    }
}

// ---------------------------------------------------------------------------
// Main: fp16 mma (fp16 acc), A fragments half-hoisted to registers,
// half2 epilogue (hfma2 + hmin2), triple-buffered y, one barrier per tile.
// 8 warps: wm = w>>2 (2), wn = w&3 (4); warp tile 64 x 32.
// ---------------------------------------------------------------------------
__global__ __launch_bounds__(256, 2)
void semidual_mma_kernel(const float* __restrict__ x) {
    extern __shared__ char smem[];
    const uint32_t sb = smem_u32(smem);
    const int tid  = threadIdx.x;
    const int lane = tid & 31;
    const int w    = tid >> 5;
    const int wm   = w >> 2;
    const int wn   = w & 3;
    const int i0   = blockIdx.x * BM;

    // cp.async one [128 x 64] fp16 y-tile with swizzled stores
    auto tile_cp = [&](int row0, uint32_t soff) {
        const char* gp = (const char*)(g_yh + (size_t)row0 * D_DIM);
#pragma unroll
        for (int it = 0; it < 4; it++) {
            int c   = it * 256 + tid;        // 0..1023
            int row = c >> 3, col = c & 7;
            uint32_t so = sb + soff + row * 128 + ((col ^ (row & 7)) << 4);
            CP_ASYNC16(so, gp + (size_t)c * 16);
        }
    };
    // pack b col-pairs for one tile into half2 smem slot
    auto bs_pack = [&](int tidx, int slot) {
        if (tid < 64) {
            float2 bv = ((const float2*)g_b)[tidx * 64 + tid];
            ((uint32_t*)(smem + OFF_BSH))[slot * 64 + tid] =
                h2_u32(__floats2half2_rn(bv.x, bv.y));
        }
    };

    // convert x tile fp32 -> fp16 directly into swizzled smem
    {
        const float4* x4 = (const float4*)(x + (size_t)i0 * D_DIM);
#pragma unroll
        for (int it = 0; it < 4; it++) {
            int c   = it * 256 + tid;        // chunk 0..1023
            int row = c >> 3, col8 = c & 7;
            float4 v0 = x4[row * 16 + col8 * 2];
            float4 v1 = x4[row * 16 + col8 * 2 + 1];
            uint4 h;
            h.x = h2_u32(__halves2half2(__float2half(v0.x), __float2half(v0.y)));
            h.y = h2_u32(__halves2half2(__float2half(v0.z), __float2half(v0.w)));
            h.z = h2_u32(__halves2half2(__float2half(v1.x), __float2half(v1.y)));
            h.w = h2_u32(__halves2half2(__float2half(v1.z), __float2half(v1.w)));
            *(uint4*)(smem + OFF_XH + row * 128 + ((col8 ^ (row & 7)) << 4)) = h;
        }
    }

    // prologue: y tiles 0,1 (separate groups); bs slots 0,1; x2
    tile_cp(0, OFF_Y);
    CP_COMMIT();
    tile_cp(BN, OFF_Y + 16384);
    CP_COMMIT();
    bs_pack(0, 0);
    bs_pack(1, 1);
    if (tid < BM) {
        const float4* xr = (const float4*)(x + (size_t)(i0 + tid) * D_DIM);
        float x2 = 0.f;
#pragma unroll
        for (int q = 0; q < 16; q++) {
            float4 v = xr[q];
            x2 = fmaf(v.x, v.x, x2); x2 = fmaf(v.y, v.y, x2);
            x2 = fmaf(v.z, v.z, x2); x2 = fmaf(v.w, v.w, x2);
        }
        ((float*)(smem + OFF_X2S))[tid] = x2;
    }
    __syncthreads();   // XH ready for A hoist

    // per-lane invariant addressing pieces
    const uint32_t axh   = sb + OFF_XH;
    const uint32_t aoff  = (uint32_t)(wm * 64 + (lane & 15)) * 128;
    const int      cselA = lane >> 4;
    const int      axorA = (lane & 7);
    const uint32_t boff  = (uint32_t)(wn * 32 + ((lane >> 4) << 3) + (lane & 7)) * 128;
    const int      cselB = (lane >> 3) & 1;
    const int      bxorB = (lane & 7);
    const int      jh    = wn * 16 + (lane & 3);   // half2 b index base

    // hoist A fragments for kb = 0,1 (x tile is invariant across y-tiles)
    uint32_t aH[4][2][4];
#pragma unroll
    for (int mt = 0; mt < 4; mt++)
#pragma unroll
        for (int kb = 0; kb < 2; kb++)
            LDSM4(aH[mt][kb],
                  axh + aoff + mt * 2048 + (uint32_t)(((2 * kb + cselA) ^ axorA) << 4));

    const __half2 m2 = __float2half2_rn(-2.0f);
    __half2 rmin2[4][2];
#pragma unroll
    for (int mt = 0; mt < 4; mt++) {
        rmin2[mt][0] = __float2half2_rn(60000.0f);
        rmin2[mt][1] = __float2half2_rn(60000.0f);
    }

    for (int t = 0; t < NTILES; t++) {
        const int b = t % 3;
        if (t + 1 < NTILES) {
            const int nb = (t + 1) % 3;
            tile_cp((t + 1) * BN, OFF_Y + nb * 16384);
            CP_COMMIT();
            bs_pack(t + 1, nb);
            CP_WAIT(1);
        } else {
            CP_WAIT(0);
        }
        __syncthreads();

        const uint32_t yb = sb + OFF_Y + b * 16384;

        uint32_t c[4][4][2];
#pragma unroll
        for (int mt = 0; mt < 4; mt++)
#pragma unroll
            for (int nt = 0; nt < 4; nt++) { c[mt][nt][0] = 0u; c[mt][nt][1] = 0u; }

#pragma unroll
        for (int kb = 0; kb < 4; kb++) {
            const uint32_t cb = (uint32_t)(((2 * kb + cselB) ^ bxorB) << 4);
            uint32_t bb[2][4];
#pragma unroll
            for (int np = 0; np < 2; np++) LDSM4(bb[np], yb + boff + np * 2048 + cb);

            if (kb < 2) {
#pragma unroll
                for (int mt = 0; mt < 4; mt++)
#pragma unroll
                    for (int nt = 0; nt < 4; nt++)
                        MMA_F16ACC(c[mt][nt], aH[mt][kb],
                                   bb[nt >> 1][(nt & 1) * 2], bb[nt >> 1][(nt & 1) * 2 + 1]);
            } else {
                uint32_t at[4][4];
                const uint32_t ca = (uint32_t)(((2 * kb + cselA) ^ axorA) << 4);
#pragma unroll
                for (int mt = 0; mt < 4; mt++) LDSM4(at[mt], axh + aoff + mt * 2048 + ca);
#pragma unroll
                for (int mt = 0; mt < 4; mt++)
#pragma unroll
                    for (int nt = 0; nt < 4; nt++)
                        MMA_F16ACC(c[mt][nt], at[mt],
                                   bb[nt >> 1][(nt & 1) * 2], bb[nt >> 1][(nt & 1) * 2 + 1]);
            }
        }

        // half2 epilogue: v = hfma2(d, -2, b_h2); rmin2 = hmin2(rmin2, v)
        const uint32_t* bh = (const uint32_t*)(smem + OFF_BSH) + b * 64;
#pragma unroll
        for (int nt = 0; nt < 4; nt++) {
            const __half2 b2 = u32_h2(bh[jh + nt * 4]);
#pragma unroll
            for (int mt = 0; mt < 4; mt++) {
                rmin2[mt][0] = __hmin2(rmin2[mt][0], __hfma2(u32_h2(c[mt][nt][0]), m2, b2));
                rmin2[mt][1] = __hmin2(rmin2[mt][1], __hfma2(u32_h2(c[mt][nt][1]), m2, b2));
            }
        }
    }

    // min across the 4 j-lanes of each row group (shuffle half2, hmin2)
#pragma unroll
    for (int mt = 0; mt < 4; mt++)
#pragma unroll
        for (int q = 0; q < 2; q++) {
            uint32_t r = h2_u32(rmin2[mt][q]);
            r = h2_u32(__hmin2(u32_h2(r), u32_h2(__shfl_xor_sync(0xffffffffu, r, 1))));
            r = h2_u32(__hmin2(u32_h2(r), u32_h2(__shfl_xor_sync(0xffffffffu, r, 2))));
            rmin2[mt][q] = u32_h2(r);
        }
    float* rowred = (float*)(smem + OFF_ROWRED);
    __syncthreads();
    if ((lane & 3) == 0) {
        const int g = lane >> 2;
#pragma unroll
        for (int mt = 0; mt < 4; mt++) {
            const int r0 = wm * 64 + mt * 16 + g;
            rowred[wn * BM + r0]     = fminf(__low2float(rmin2[mt][0]), __high2float(rmin2[mt][0]));
            rowred[wn * BM + r0 + 8] = fminf(__low2float(rmin2[mt][1]), __high2float(rmin2[mt][1]));
        }
    }
    __syncthreads();
    if (tid < BM) {
        float m = fminf(fminf(rowred[tid], rowred[BM + tid]),
                        fminf(rowred[2 * BM + tid], rowred[3 * BM + tid]));
        float v = ((const float*)(smem + OFF_X2S))[tid] + m;
#pragma unroll
        for (int s = 16; s >= 1; s >>= 1) v += __shfl_xor_sync(0xffffffffu, v, s);
        if (lane == 0) ((float*)(smem + OFF_RED))[tid >> 5] = v;
    }
    __syncthreads();
    if (tid == 0) {
        const float* rd = (const float*)(smem + OFF_RED);
        g_partials[blockIdx.x] = rd[0] + rd[1] + rd[2] + rd[3];
    }
}

// ---------------------------------------------------------------------------
// Finalize: deterministic reduction + mean(psi), vectorized
// ---------------------------------------------------------------------------
__global__ void finalize_kernel(const float* __restrict__ psi,
                                float* __restrict__ out) {
    __shared__ float sh[256];
    int tid = threadIdx.x;
    float s = 0.f;
    for (int b = tid; b < NBLOCKS; b += 256) s += g_partials[b];
    s *= (1.0f / N_PTS);
    float p = 0.f;
    const float4* p4 = (const float4*)psi;
#pragma unroll
    for (int q = 0; q < M_PTS / 4 / 256; q++) {
        float4 v = p4[q * 256 + tid];
        p += (v.x + v.y) + (v.z + v.w);
    }
    s = fmaf(p, 1.0f / M_PTS, s);
    sh[tid] = s;
    __syncthreads();
    for (int off = 128; off > 0; off >>= 1) {
        if (tid < off) sh[tid] += sh[tid + off];
        __syncthreads();
    }
    if (tid == 0) out[0] = sh[0];
}

extern "C" void kernel_launch(void* const* d_in, const int* in_sizes, int n_in,
                              void* d_out, int out_size) {
    (void)in_sizes; (void)n_in; (void)out_size;
    const float* x   = (const float*)d_in[0];   // [N, D]
    const float* y   = (const float*)d_in[1];   // [M, D]
    const float* psi = (const float*)d_in[2];   // [M]
    float* out = (float*)d_out;

    cudaFuncSetAttribute(semidual_mma_kernel,
                         cudaFuncAttributeMaxDynamicSharedMemorySize, SMEM_TOTAL);

    prep_y_kernel<<<(M_PTS * D_DIM / 4) / 256, 256>>>(y, psi);
    semidual_mma_kernel<<<NBLOCKS, 256, SMEM_TOTAL>>>(x);
    finalize_kernel<<<1, 256>>>(psi, out);
}